// round 6
// baseline (speedup 1.0000x reference)
#include <cuda_runtime.h>
#include <cstdint>

// ============================================================================
// NNLS via normal equations on mma.sync tf32 (base PTX -- no arch-'a').
//   B = [X(32)|y(4)|ones(1)|pad(3)] (40 cols), 64-row tiles, stride 40.
//   hi = x & 0xFFFFE000 (exact tf32), lo = x - hi.
//   P1 += H^T H, P2 += H^T L  (m16n8k8 tf32 MMAs, f32 reg accumulators)
//   G40 = P1 + P2 + P2^T ; then tiny projected-gradient QP solve.
// ============================================================================

#define TPB 256
#define NCTA 296
#define STRIDE 40
#define TSZ 2576          // 64*40 + wrap guard for mi=2 A-frag overreads
#define PGD_ITERS 48

__device__ float ACC1[1600];   // P1 (hi*hi), 40x40
__device__ float ACC2[1600];   // P2 (hi*lo), 40x40

__global__ void zero_acc_kernel() {
    int t = blockIdx.x * blockDim.x + threadIdx.x;
    if (t < 1600) { ACC1[t] = 0.0f; ACC2[t] = 0.0f; }
}

static __device__ __forceinline__ void mma_tf32(float* d, const uint32_t* a,
                                                const uint32_t* b) {
    asm volatile(
        "mma.sync.aligned.m16n8k8.row.col.f32.tf32.tf32.f32 "
        "{%0,%1,%2,%3}, {%4,%5,%6,%7}, {%8,%9}, {%0,%1,%2,%3};"
        : "+f"(d[0]), "+f"(d[1]), "+f"(d[2]), "+f"(d[3])
        : "r"(a[0]), "r"(a[1]), "r"(a[2]), "r"(a[3]), "r"(b[0]), "r"(b[1]));
}

static __device__ __forceinline__ float himask(float x) {
    return __uint_as_float(__float_as_uint(x) & 0xFFFFE000u);
}

// ---------------------------------------------------------------------------
__global__ __launch_bounds__(TPB, 2) void gram_kernel(
    const float* __restrict__ X, const float* __restrict__ Y,
    int N, int ntiles)
{
    __shared__ __align__(16) float TH[2][TSZ];
    __shared__ __align__(16) float TL[2][TSZ];

    const int tid = threadIdx.x;
    const int w   = tid >> 5;
    const int l   = tid & 31;
    const int gid = l >> 2;    // fragment group 0..7
    const int tig = l & 3;     // thread-in-group

    // zero prefill (pad cols 37..39 + guard stay zero forever)
    for (int e = tid; e < TSZ; e += TPB) {
        TH[0][e] = 0.f; TH[1][e] = 0.f; TL[0][e] = 0.f; TL[1][e] = 0.f;
    }

    // warp roles: w<6: side=w&1 (0:P1/H, 1:P2/L), mi=w>>1, positions nj=0..3
    //             w>=6: side=w-6, nj=4, positions mi=0..2
    const int side = (w < 6) ? (w & 1) : (w - 6);
    const int mi0  = (w < 6) ? (w >> 1) : 0;

    float acc[4][4];
#pragma unroll
    for (int q = 0; q < 4; q++)
#pragma unroll
        for (int e = 0; e < 4; e++) acc[q][e] = 0.f;

    const int bx = blockIdx.x;
    const int nloc = (ntiles > bx) ? (ntiles - 1 - bx) / (int)gridDim.x + 1 : 0;

    // staging: thread -> (row xrow, colgroup xcg) of the 64x32 X slab
    const int xrow = tid >> 2;
    const int xcg  = (tid & 3) * 8;
    float4 xa, xb, yv;
    int valid = 0, yvalid = 0;
    const float4 z4 = make_float4(0.f, 0.f, 0.f, 0.f);

    auto prefetch = [&](int i) {
        long long g = (long long)bx + (long long)i * gridDim.x;
        long long r = g * 64 + xrow;
        valid = (r < (long long)N);
        if (valid) {
            const float4* p = (const float4*)(X + r * 32 + xcg);
            xa = p[0]; xb = p[1];
        } else { xa = z4; xb = z4; }
        if (tid < 64) {
            long long ry = g * 64 + tid;
            yvalid = (ry < (long long)N);
            yv = yvalid ? ((const float4*)Y)[ry] : z4;
        }
    };

    auto store = [&](int p) {
        float* th = TH[p]; float* tl = TL[p];
        const int base = xrow * STRIDE + xcg;
        float4 ha, hb, la, lb;
        ha.x = himask(xa.x); la.x = xa.x - ha.x;
        ha.y = himask(xa.y); la.y = xa.y - ha.y;
        ha.z = himask(xa.z); la.z = xa.z - ha.z;
        ha.w = himask(xa.w); la.w = xa.w - ha.w;
        hb.x = himask(xb.x); lb.x = xb.x - hb.x;
        hb.y = himask(xb.y); lb.y = xb.y - hb.y;
        hb.z = himask(xb.z); lb.z = xb.z - hb.z;
        hb.w = himask(xb.w); lb.w = xb.w - hb.w;
        *(float4*)(th + base)     = ha;
        *(float4*)(th + base + 4) = hb;
        *(float4*)(tl + base)     = la;
        *(float4*)(tl + base + 4) = lb;
        if (tid < 64) {
            const int b2 = tid * STRIDE + 32;
            float4 hy, ly;
            hy.x = himask(yv.x); ly.x = yv.x - hy.x;
            hy.y = himask(yv.y); ly.y = yv.y - hy.y;
            hy.z = himask(yv.z); ly.z = yv.z - hy.z;
            hy.w = himask(yv.w); ly.w = yv.w - hy.w;
            *(float4*)(th + b2) = hy;
            *(float4*)(tl + b2) = ly;
            th[tid * STRIDE + 36] = yvalid ? 1.0f : 0.0f;   // ones col (validity)
        }
    };

    if (nloc > 0) { prefetch(0); store(0); }
    __syncthreads();

    for (int i = 0; i < nloc; i++) {
        const int p = i & 1;
        if (i + 1 < nloc) prefetch(i + 1);

        const float* H  = TH[p];
        const float* Bm = side ? TL[p] : TH[p];
        // per-warp fragment base offsets
        const int aoff = tig * STRIDE + gid;         // + k0*STRIDE (+ mi*16)
        const int boff = tig * STRIDE + gid;         // + k0*STRIDE + nj*8

#pragma unroll
        for (int ks = 0; ks < 8; ks++) {
            const int k0s = ks * 8 * STRIDE;
            if (w < 6) {
                uint32_t a[4];
                const float* Ha = H + k0s + aoff + mi0 * 16;
                a[0] = __float_as_uint(Ha[0]);
                a[1] = __float_as_uint(Ha[8]);
                a[2] = __float_as_uint(Ha[4 * STRIDE]);
                a[3] = __float_as_uint(Ha[4 * STRIDE + 8]);
                const float* Bb = Bm + k0s + boff;
#pragma unroll
                for (int q = 0; q < 4; q++) {
                    uint32_t b[2];
                    b[0] = __float_as_uint(Bb[q * 8]);
                    b[1] = __float_as_uint(Bb[q * 8 + 4 * STRIDE]);
                    mma_tf32(acc[q], a, b);
                }
            } else {
                uint32_t b[2];
                const float* Bb = Bm + k0s + boff + 32;   // nj = 4
                b[0] = __float_as_uint(Bb[0]);
                b[1] = __float_as_uint(Bb[4 * STRIDE]);
                const float* Ha = H + k0s + aoff;
#pragma unroll
                for (int q = 0; q < 3; q++) {
                    uint32_t a[4];
                    a[0] = __float_as_uint(Ha[q * 16]);
                    a[1] = __float_as_uint(Ha[q * 16 + 8]);
                    a[2] = __float_as_uint(Ha[q * 16 + 4 * STRIDE]);
                    a[3] = __float_as_uint(Ha[q * 16 + 4 * STRIDE + 8]);
                    mma_tf32(acc[q], a, b);
                }
            }
        }

        if (i + 1 < nloc) store(p ^ 1);
        __syncthreads();
    }

    // ---- epilogue: atomicAdd fragments into ACC1/ACC2 ----
    if (nloc > 0) {
        float* dst = side ? ACC2 : ACC1;
        const int npos = (w < 6) ? 4 : 3;
#pragma unroll
        for (int q = 0; q < 4; q++) {
            if (q >= npos) break;
            const int mi = (w < 6) ? mi0 : q;
            const int nj = (w < 6) ? q : 4;
            const int i0 = mi * 16 + gid;
            const int j0 = nj * 8 + 2 * tig;
            if (i0 < 40) {
                atomicAdd(&dst[i0 * 40 + j0],     acc[q][0]);
                atomicAdd(&dst[i0 * 40 + j0 + 1], acc[q][1]);
            }
            if (i0 + 8 < 40) {
                atomicAdd(&dst[(i0 + 8) * 40 + j0],     acc[q][2]);
                atomicAdd(&dst[(i0 + 8) * 40 + j0 + 1], acc[q][3]);
            }
        }
    }
}

// ---------------------------------------------------------------------------
__global__ __launch_bounds__(256) void solve_kernel(float* __restrict__ out)
{
    __shared__ float G[33 * 33];
    __shared__ float c[132];
    __shared__ float Z[132];
    __shared__ float rowsum[33];
    __shared__ float stepSh;

    const int tid = threadIdx.x;
    // G40(a,b) = P1[a][b] + P2[a][b] + P2[b][a]; map i33: i<32 -> i, 32 -> 36
    for (int e = tid; e < 33 * 33; e += 256) {
        int i = e / 33, j = e % 33;
        int a = (i < 32) ? i : 36, b = (j < 32) ? j : 36;
        G[e] = ACC1[a * 40 + b] + ACC2[a * 40 + b] + ACC2[b * 40 + a];
    }
    if (tid < 132) {
        int i = tid >> 2, m = tid & 3;
        int a = (i < 32) ? i : 36;
        c[tid] = ACC1[a * 40 + 32 + m] + ACC2[a * 40 + 32 + m]
               + ACC2[(32 + m) * 40 + a];
        Z[tid] = 0.0f;
    }
    __syncthreads();

    if (tid < 33) {
        float s = 0.f;
        for (int j = 0; j < 33; j++) s += fabsf(G[tid * 33 + j]);
        rowsum[tid] = s;
    }
    __syncthreads();
    if (tid == 0) {
        float L = 0.f;
        for (int i = 0; i < 33; i++) L = fmaxf(L, rowsum[i]);
        stepSh = 1.0f / L;
    }
    __syncthreads();
    const float step = stepSh;

    const int i = tid >> 2, m = tid & 3;
    for (int it = 0; it < PGD_ITERS; it++) {
        float zn = 0.f;
        if (tid < 132) {
            float dot = 0.f;
#pragma unroll
            for (int j = 0; j < 33; j++) dot += G[i * 33 + j] * Z[j * 4 + m];
            zn = Z[tid] - step * (dot - c[tid]);
            if (i < 32) zn = fmaxf(zn, 0.0f);
        }
        __syncthreads();
        if (tid < 132) Z[tid] = zn;
        __syncthreads();
    }
    if (tid < 128) out[tid] = Z[tid];
}

// ---------------------------------------------------------------------------
extern "C" void kernel_launch(void* const* d_in, const int* in_sizes, int n_in,
                              void* d_out, int out_size)
{
    const float* X = (const float*)d_in[0];
    const float* Y = (const float*)d_in[1];
    const int N = in_sizes[0] / 32;
    const int ntiles = (N + 63) / 64;

    zero_acc_kernel<<<7, 256>>>();
    gram_kernel<<<NCTA, TPB>>>(X, Y, N, ntiles);
    solve_kernel<<<1, 256>>>((float*)d_out);
}